// round 7
// baseline (speedup 1.0000x reference)
#include <cuda_runtime.h>
#include <math_constants.h>

#define N 512
#define D 64
#define MAX_STEPS 10

// ---- persistent scratch (no allocations allowed) ----
__device__ float        g_p0[N];
__device__ unsigned int g_cand[MAX_STEPS][N];   // per-step candidate maxima (float bits)
__device__ float        g_rowconst[N * D];      // nf[i]@W1[0:64] + b1
__device__ float        g_Bt[D * N];            // (nf[j]@W1[64:128])^T : [k][j]
__device__ float        g_f0[N];                // node_features[:,0]

// ---------------------------------------------------------------------------
__global__ void k_init_state(const int* __restrict__ shock, int n_shock) {
    int t = threadIdx.x;                    // 512 threads
    if (t < N) g_p0[t] = 0.f;
    unsigned int* c = &g_cand[0][0];
    for (int idx = t; idx < MAX_STEPS * N; idx += 512) c[idx] = 0u;
    __syncthreads();
    if (t < n_shock) g_p0[shock[t]] = 1.f;
}

// 128 blocks x 256: one elem of rowconst and Bt each.
__global__ void k_init_ab(const float* __restrict__ nf,
                          const float* __restrict__ W1,
                          const float* __restrict__ b1) {
    int gid = blockIdx.x * 256 + threadIdx.x;      // < 32768
    int i = gid >> 6, k = gid & 63;
    float accA = b1[k];
#pragma unroll 8
    for (int d = 0; d < D; d++) accA = fmaf(nf[i * D + d], W1[d * D + k], accA);
    g_rowconst[gid] = accA;

    int j = gid & (N - 1), kk = gid >> 9;
    float accB = 0.f;
#pragma unroll 8
    for (int d = 0; d < D; d++) accB = fmaf(nf[j * D + d], W1[(D + d) * D + kk], accB);
    g_Bt[kk * N + j] = accB;

    if (gid < N) g_f0[gid] = nf[gid * D];
}

// ---------------------------------------------------------------------------
// Step kernel. Block = 8 src rows x 32 targets. Warps 0-3 compute m[0:16),
// warps 4-7 compute m[16:32), for rows (warp&3) and (warp&3)+4. Each thread
// owns 2 edges x 16 m's: 8+8 u64 accumulators -> ~80 regs -> 3 CTAs/SM.
__global__ void __launch_bounds__(256, 3)
k_edges(const float* __restrict__ cgm, const float* __restrict__ W1,
        const float* __restrict__ W2,  const float* __restrict__ b2,
        const float* __restrict__ W3,  const float* __restrict__ b3,
        int step, float sf) {
    __shared__ __align__(16) float s_w2[D * 32];   // W2[k][m]
    __shared__ __align__(16) float s_bt2[D * 32];  // Bt interleaved: [k2][lane] float2
    __shared__ __align__(16) float s_rv[8 * D];    // per-(row,k) affine row vector
    __shared__ __align__(16) float s_wq[2 * D];    // (w128[k], w131[k]) interleaved
    __shared__ float s_w3[32];
    __shared__ unsigned long long s_b2p[16];       // b2 packed pairs
    __shared__ float s_z[2 * 8 * 32];              // partial z per (mhalf,row,lane)
    __shared__ float s_cg[8 * 32];                 // cg tile for finalize
    __shared__ float s_f0i[8], s_f0j[32], s_pi[8];
    __shared__ unsigned int s_cand[32];
    __shared__ float s_b3;
    __shared__ int s_alive;

    int tid = threadIdx.x;
    int warp = tid >> 5, lane = tid & 31;
    int j0 = blockIdx.x * 32;
    int i0 = blockIdx.y * 8;

    if (tid == 0) s_alive = 0;
    __syncthreads();
    if (tid < 8) {
        float p = g_p0[i0 + tid];                  // replay: p_s = max(p0, cand_0..s-1)
        for (int s = 0; s < step; s++)
            p = fmaxf(p, __uint_as_float(g_cand[s][i0 + tid]));
        s_pi[tid] = p;
        s_f0i[tid] = g_f0[i0 + tid];
        if (p > 0.f) atomicExch(&s_alive, 1);
    }
    if (tid < 32) { s_f0j[tid] = g_f0[j0 + tid]; s_w3[tid] = W3[tid]; s_cand[tid] = 0u; }
    __syncthreads();
    if (!s_alive) return;                          // dead block: skip tile loads too

    {   // tile loads
        const float4* W24 = (const float4*)W2;
        float4* s_w24 = (float4*)s_w2;
        for (int idx = tid; idx < 512; idx += 256) s_w24[idx] = W24[idx];
        for (int idx = tid; idx < 2048; idx += 256) {
            int k = idx >> 5, l = idx & 31;        // interleave k-pairs
            s_bt2[((k >> 1) << 6) + (l << 1) + (k & 1)] = g_Bt[k * N + j0 + l];
        }
        for (int idx = tid; idx < 512; idx += 256) {
            int r = idx >> 6, k = idx & 63;
            s_rv[idx] = fmaf(s_pi[r], W1[129 * D + k],
                        fmaf(sf, W1[130 * D + k], g_rowconst[(i0 + r) * D + k]));
        }
        if (tid < 128) s_wq[tid] = W1[(128 + 3 * (tid & 1)) * D + (tid >> 1)];
        if (tid < 16) {
            unsigned long long pk;
            asm("mov.b64 %0, {%1, %2};" : "=l"(pk) : "f"(b2[2 * tid]), "f"(b2[2 * tid + 1]));
            s_b2p[tid] = pk;
        }
        if (tid == 0) s_b3 = b3[0];
    }
    __syncthreads();

    int mhalf = warp >> 2;                         // 0 or 1: owns m[16*mhalf, +16)
    int moff = mhalf << 4;
    int ra = warp & 3, rb = ra + 4;
    float p_ia = s_pi[ra], p_ib = s_pi[rb];
    if (p_ia > 0.f || p_ib > 0.f) {
        float cga = cgm[(i0 + ra) * N + j0 + lane];
        float cgb = cgm[(i0 + rb) * N + j0 + lane];
        if (mhalf == 0) { s_cg[ra * 32 + lane] = cga; s_cg[rb * 32 + lane] = cgb; }
        float fda = fabsf(s_f0i[ra] - s_f0j[lane]);
        float fdb = fabsf(s_f0i[rb] - s_f0j[lane]);
        unsigned long long h2a[8], h2b[8];         // 16 m's each (8 f32 pairs)
#pragma unroll
        for (int q = 0; q < 8; q++) { h2a[q] = s_b2p[mhalf * 8 + q]; h2b[q] = h2a[q]; }
        const float4* wq4 = (const float4*)s_wq;
        const float2* bt2 = (const float2*)s_bt2;
        const float2* rva2 = (const float2*)(&s_rv[ra * D]);
        const float2* rvb2 = (const float2*)(&s_rv[rb * D]);
#pragma unroll 2
        for (int k2 = 0; k2 < 32; k2++) {
            float4 wq = wq4[k2];                   // LDS.128 broadcast: (w128,w131) x2 k's
            float2 bt = bt2[(k2 << 5) + lane];     // LDS.64 per-lane
            float2 rva = rva2[k2];                 // LDS.64 broadcast
            float2 rvb = rvb2[k2];
            float h1a0 = fmaxf(fmaf(cga, wq.x, fmaf(fda, wq.y, rva.x + bt.x)), 0.f);
            float h1a1 = fmaxf(fmaf(cga, wq.z, fmaf(fda, wq.w, rva.y + bt.y)), 0.f);
            float h1b0 = fmaxf(fmaf(cgb, wq.x, fmaf(fdb, wq.y, rvb.x + bt.x)), 0.f);
            float h1b1 = fmaxf(fmaf(cgb, wq.z, fmaf(fdb, wq.w, rvb.y + bt.y)), 0.f);
            unsigned long long a0, a1, b0, b1;
            asm("mov.b64 %0, {%1, %1};" : "=l"(a0) : "f"(h1a0));
            asm("mov.b64 %0, {%1, %1};" : "=l"(a1) : "f"(h1a1));
            asm("mov.b64 %0, {%1, %1};" : "=l"(b0) : "f"(h1b0));
            asm("mov.b64 %0, {%1, %1};" : "=l"(b1) : "f"(h1b1));
            // k-row 2*k2 weights multiply h1 of row 2*k2 (a0/b0):
            const ulonglong2* w0 = (const ulonglong2*)&s_w2[((2 * k2) << 5) + moff];
#pragma unroll
            for (int q = 0; q < 4; q++) {
                ulonglong2 v = w0[q];              // LDS.128 -> 8 FFMA2
                asm("fma.rn.f32x2 %0, %1, %2, %0;" : "+l"(h2a[2 * q])     : "l"(a0), "l"(v.x));
                asm("fma.rn.f32x2 %0, %1, %2, %0;" : "+l"(h2a[2 * q + 1]) : "l"(a0), "l"(v.y));
                asm("fma.rn.f32x2 %0, %1, %2, %0;" : "+l"(h2b[2 * q])     : "l"(b0), "l"(v.x));
                asm("fma.rn.f32x2 %0, %1, %2, %0;" : "+l"(h2b[2 * q + 1]) : "l"(b0), "l"(v.y));
            }
            // k-row 2*k2+1 weights multiply h1 of row 2*k2+1 (a1/b1):
            const ulonglong2* w1 = (const ulonglong2*)&s_w2[((2 * k2 + 1) << 5) + moff];
#pragma unroll
            for (int q = 0; q < 4; q++) {
                ulonglong2 v = w1[q];              // LDS.128 -> 8 FFMA2
                asm("fma.rn.f32x2 %0, %1, %2, %0;" : "+l"(h2a[2 * q])     : "l"(a1), "l"(v.x));
                asm("fma.rn.f32x2 %0, %1, %2, %0;" : "+l"(h2a[2 * q + 1]) : "l"(a1), "l"(v.y));
                asm("fma.rn.f32x2 %0, %1, %2, %0;" : "+l"(h2b[2 * q])     : "l"(b1), "l"(v.x));
                asm("fma.rn.f32x2 %0, %1, %2, %0;" : "+l"(h2b[2 * q + 1]) : "l"(b1), "l"(v.y));
            }
        }
        // layer 3 partials over this thread's 16 m's
        float za = 0.f, zb = 0.f;
#pragma unroll
        for (int q = 0; q < 8; q++) {
            float lo, hi;
            asm("mov.b64 {%0, %1}, %2;" : "=f"(lo), "=f"(hi) : "l"(h2a[q]));
            za = fmaf(fmaxf(lo, 0.f), s_w3[moff + 2 * q], za);
            za = fmaf(fmaxf(hi, 0.f), s_w3[moff + 2 * q + 1], za);
            asm("mov.b64 {%0, %1}, %2;" : "=f"(lo), "=f"(hi) : "l"(h2b[q]));
            zb = fmaf(fmaxf(lo, 0.f), s_w3[moff + 2 * q], zb);
            zb = fmaf(fmaxf(hi, 0.f), s_w3[moff + 2 * q + 1], zb);
        }
        s_z[mhalf * 256 + ra * 32 + lane] = za;
        s_z[mhalf * 256 + rb * 32 + lane] = zb;
    }
    __syncthreads();

    // finalize: thread (warp=row 0..7, lane=j)
    {
        float p_i = s_pi[warp];
        float val = 0.f;
        if (p_i > 0.f) {
            float cg = s_cg[warp * 32 + lane];
            if (cg > 0.f) {
                float z = s_z[warp * 32 + lane] + s_z[256 + warp * 32 + lane] + s_b3;
                float t = 1.f / (1.f + __expf(-z));
                val = p_i * t * cg;
            }
        }
        if (val > 0.f) atomicMax(&s_cand[lane], __float_as_uint(val));  // >=0: uint==float order
    }
    __syncthreads();
    if (tid < 32) {
        unsigned v = s_cand[tid];
        if (v) atomicMax(&g_cand[step][j0 + tid], v);
    }
}

// replay the 10-step max/arr recurrence exactly; write output
__global__ void k_final(float* __restrict__ out) {
    int j = threadIdx.x;                           // 512 threads
    float p = g_p0[j];
    float arr = (p > 0.f) ? 0.f : CUDART_INF_F;
#pragma unroll
    for (int s = 0; s < MAX_STEPS; s++) {
        float c = __uint_as_float(g_cand[s][j]);
        if (c > p) { p = c; arr = fminf(arr, (float)(s + 1)); }
    }
    out[j] = p; out[N + j] = arr;
}

// ---------------------------------------------------------------------------
extern "C" void kernel_launch(void* const* d_in, const int* in_sizes, int n_in,
                              void* d_out, int out_size) {
    const float* cg    = (const float*)d_in[0];
    const float* nf    = (const float*)d_in[1];
    const int*   shock = (const int*)  d_in[2];
    const float* W1    = (const float*)d_in[3];
    const float* b1    = (const float*)d_in[4];
    const float* W2    = (const float*)d_in[5];
    const float* b2    = (const float*)d_in[6];
    const float* W3    = (const float*)d_in[7];
    const float* b3    = (const float*)d_in[8];
    float* out = (float*)d_out;

    k_init_state<<<1, 512>>>(shock, in_sizes[2]);
    k_init_ab<<<128, 256>>>(nf, W1, b1);
    for (int s = 0; s < MAX_STEPS; s++)
        k_edges<<<dim3(16, 64), 256>>>(cg, W1, W2, b2, W3, b3,
                                       s, (float)s / (float)MAX_STEPS);
    k_final<<<1, 512>>>(out);
}